// round 6
// baseline (speedup 1.0000x reference)
#include <cuda_runtime.h>
#include <cuda_fp16.h>
#include <stdint.h>

#define N_NODES 100000
#define N_EDGES 3200000
#define D 128
#define LN_EPS 1e-5f

// ---------------------------------------------------------------------------
// Device-global scratch (no allocations allowed).
// ---------------------------------------------------------------------------
__device__ __half g_Hh[(size_t)N_NODES * D];   // LN(X) @ W^T + b, fp16
__device__ int   g_off[N_NODES + 1];           // CSR offsets (by dst)
__device__ int   g_cur[N_NODES];               // bucket cursors
__device__ int2  g_sw[N_EDGES];                // packed (src, w_bits) sorted by dst
__device__ int   g_bsum[128];                  // scan block sums

// ===========================================================================
// Kernel 1: fused [LayerNorm + Linear -> g_Hh (fp16)]  +  [edge histogram].
// ===========================================================================
#define ROWS_PB 32
#define LN_BLOCKS (N_NODES / ROWS_PB)              // 3125
#define HIST_BLOCKS 1024
#define WS_PITCH 132
#define XN2_OFF (128 * WS_PITCH)                   // in floats
#define SMEM_BYTES ((128 * WS_PITCH) * 4 + ROWS_PB * D * 8)

__global__ void __launch_bounds__(256, 2)
ln_linear_hist_kernel(const float* __restrict__ X,
                      const float* __restrict__ gamma,
                      const float* __restrict__ beta,
                      const float* __restrict__ W,
                      const float* __restrict__ bias,
                      const int* __restrict__ edst, int E) {
    const int tid = threadIdx.x;

    // ---- histogram role -------------------------------------------------
    if (blockIdx.x >= LN_BLOCKS) {
        const int hb     = blockIdx.x - LN_BLOCKS;
        const int stride = HIST_BLOCKS * 256;
        for (int e = hb * 256 + tid; e < E; e += stride)
            atomicAdd(&g_off[__ldcs(&edst[e]) + 1], 1);
        return;
    }

    // ---- LN + GEMM role -------------------------------------------------
    extern __shared__ float smem[];
    float*  Ws  = smem;                                       // [128][132]
    float2* xn2 = reinterpret_cast<float2*>(smem + XN2_OFF);  // splatted {x,x}

    const int lane = tid & 31;
    const int warp = tid >> 5;
    const int row0 = blockIdx.x * ROWS_PB;

    // Load + transpose W into smem.
    for (int i = tid; i < 128 * 128; i += 256) {
        int o = i >> 7;
        int d = i & 127;
        Ws[d * WS_PITCH + o] = W[i];
    }

    // LayerNorm: 8 warps x 4 rows each; write splatted pairs {h,h}.
    #pragma unroll
    for (int rr = 0; rr < ROWS_PB / 8; ++rr) {
        const int r   = warp + rr * 8;
        const int row = row0 + r;
        const float4 v = reinterpret_cast<const float4*>(X + (size_t)row * D)[lane];
        float s  = v.x + v.y + v.z + v.w;
        float sq = v.x * v.x + v.y * v.y + v.z * v.z + v.w * v.w;
        #pragma unroll
        for (int off = 16; off; off >>= 1) {
            s  += __shfl_xor_sync(0xffffffffu, s,  off);
            sq += __shfl_xor_sync(0xffffffffu, sq, off);
        }
        const float mu  = s * (1.0f / D);
        const float var = sq * (1.0f / D) - mu * mu;
        const float inv = rsqrtf(var + LN_EPS);
        const float4 g  = reinterpret_cast<const float4*>(gamma)[lane];
        const float4 be = reinterpret_cast<const float4*>(beta)[lane];
        float h0 = (v.x - mu) * inv * g.x + be.x;
        float h1 = (v.y - mu) * inv * g.y + be.y;
        float h2 = (v.z - mu) * inv * g.z + be.z;
        float h3 = (v.w - mu) * inv * g.w + be.w;
        float2* xp = xn2 + r * D + lane * 4;
        xp[0] = make_float2(h0, h0);
        xp[1] = make_float2(h1, h1);
        xp[2] = make_float2(h2, h2);
        xp[3] = make_float2(h3, h3);
    }
    __syncthreads();

    // GEMM: thread (tr, tc): rows tr*4..+3, cols tc*4..+3. f32x2 packed FMA.
    const int tc = tid & 31;
    const int tr = tid >> 5;

    unsigned long long acc01[4], acc23[4];
    #pragma unroll
    for (int i = 0; i < 4; ++i) { acc01[i] = 0ull; acc23[i] = 0ull; }

    const unsigned long long* xbase =
        reinterpret_cast<const unsigned long long*>(xn2) + tr * 4 * D;
    const float* wbase = Ws + (tc << 2);

    #pragma unroll 4
    for (int d = 0; d < D; ++d) {
        const ulonglong2 wv =
            *reinterpret_cast<const ulonglong2*>(wbase + d * WS_PITCH);
        #pragma unroll
        for (int r = 0; r < 4; ++r) {
            const unsigned long long xs = xbase[r * D + d];   // {x,x}
            asm("fma.rn.f32x2 %0, %1, %2, %0;" : "+l"(acc01[r]) : "l"(xs), "l"(wv.x));
            asm("fma.rn.f32x2 %0, %1, %2, %0;" : "+l"(acc23[r]) : "l"(xs), "l"(wv.y));
        }
    }

    const float4 bv = reinterpret_cast<const float4*>(bias)[tc];
    #pragma unroll
    for (int r = 0; r < 4; ++r) {
        const int row = row0 + tr * 4 + r;
        const float hx = __uint_as_float((unsigned)(acc01[r] & 0xffffffffull)) + bv.x;
        const float hy = __uint_as_float((unsigned)(acc01[r] >> 32))           + bv.y;
        const float hz = __uint_as_float((unsigned)(acc23[r] & 0xffffffffull)) + bv.z;
        const float hw = __uint_as_float((unsigned)(acc23[r] >> 32))           + bv.w;
        const __half2 p01 = __floats2half2_rn(hx, hy);
        const __half2 p23 = __floats2half2_rn(hz, hw);
        uint2 st;
        st.x = *reinterpret_cast<const unsigned*>(&p01);
        st.y = *reinterpret_cast<const unsigned*>(&p23);
        reinterpret_cast<uint2*>(g_Hh + (size_t)row * D)[tc] = st;
    }
}

// ===========================================================================
// CSR build: scan + reorder (histogram fused above)
// ===========================================================================
__device__ __forceinline__ int warp_incl_scan(int v, int lane) {
    #pragma unroll
    for (int off = 1; off < 32; off <<= 1) {
        int t = __shfl_up_sync(0xffffffffu, v, off);
        if (lane >= off) v += t;
    }
    return v;
}

__global__ void scan_chunk_kernel(int n) {        // blockDim = 1024
    __shared__ int wsum[32];
    const int tid  = threadIdx.x;
    const int lane = tid & 31;
    const int wid  = tid >> 5;
    const int gi   = blockIdx.x * 1024 + tid;
    int v = (gi < n) ? g_off[gi] : 0;
    v = warp_incl_scan(v, lane);
    if (lane == 31) wsum[wid] = v;
    __syncthreads();
    if (wid == 0) wsum[lane] = warp_incl_scan(wsum[lane], lane);
    __syncthreads();
    if (wid > 0) v += wsum[wid - 1];
    if (gi < n) g_off[gi] = v;
    if (tid == 1023) g_bsum[blockIdx.x] = v;
}

__global__ void scan_bsum_kernel(int nb) {        // 1 block, 128 threads
    __shared__ int wsum[4];
    const int tid  = threadIdx.x;
    const int lane = tid & 31;
    const int wid  = tid >> 5;
    int v = (tid < nb) ? g_bsum[tid] : 0;
    v = warp_incl_scan(v, lane);
    if (lane == 31) wsum[wid] = v;
    __syncthreads();
    int add = 0;
    #pragma unroll
    for (int w = 0; w < 4; ++w) add += (w < wid) ? wsum[w] : 0;
    if (tid < nb) g_bsum[tid] = v + add;
}

__global__ void scan_add_kernel(int n) {          // blockDim = 1024
    const int gi = blockIdx.x * 1024 + threadIdx.x;
    if (gi >= n) return;
    const int add = (blockIdx.x > 0) ? g_bsum[blockIdx.x - 1] : 0;
    const int val = g_off[gi] + add;
    g_off[gi] = val;
    if (gi < N_NODES) g_cur[gi] = val;
}

__global__ void reorder_kernel(const int* __restrict__ esrc,
                               const int* __restrict__ edst,
                               const float* __restrict__ ew, int E) {
    const int stride = gridDim.x * blockDim.x;
    for (int e = blockIdx.x * blockDim.x + threadIdx.x; e < E; e += stride) {
        const int dst = __ldcs(&edst[e]);
        const int pos = atomicAdd(&g_cur[dst], 1);
        g_sw[pos] = make_int2(__ldcs(&esrc[e]), __float_as_int(__ldcs(&ew[e])));
    }
}

// ===========================================================================
// Aggregate: TWO nodes per warp (16 lanes each).
//   Lane loads uint4 = 16B of the 256B fp16 row; fp32 accumulate; unroll-2.
//   out = relu(sum w*H[src]) + X.
// ===========================================================================
__device__ __forceinline__ void fma_h8(float* acc, uint4 raw, float w) {
    const __half2* hp = reinterpret_cast<const __half2*>(&raw);
    #pragma unroll
    for (int i = 0; i < 4; ++i) {
        const float2 f = __half22float2(hp[i]);
        acc[2 * i + 0] = fmaf(w, f.x, acc[2 * i + 0]);
        acc[2 * i + 1] = fmaf(w, f.y, acc[2 * i + 1]);
    }
}

__global__ void __launch_bounds__(256)
aggregate_kernel(const float* __restrict__ X, float* __restrict__ out) {
    const int gw = (blockIdx.x * blockDim.x + threadIdx.x) >> 5;
    const int lane = threadIdx.x & 31;
    const int half = lane >> 4;               // 0 or 1: which node
    const int hl   = lane & 15;               // lane within half-warp
    const int node = gw * 2 + half;
    if (node >= N_NODES) return;

    const int beg = g_off[node];
    const int end = g_off[node + 1];

    float acc[8];
    #pragma unroll
    for (int i = 0; i < 8; ++i) acc[i] = 0.f;

    int e = beg;
    for (; e + 1 < end; e += 2) {             // unroll-2 for gather MLP
        const int2 sw0 = __ldcs(&g_sw[e]);
        const int2 sw1 = __ldcs(&g_sw[e + 1]);
        const uint4 r0 = __ldg(
            reinterpret_cast<const uint4*>(g_Hh + (size_t)sw0.x * D) + hl);
        const uint4 r1 = __ldg(
            reinterpret_cast<const uint4*>(g_Hh + (size_t)sw1.x * D) + hl);
        fma_h8(acc, r0, __int_as_float(sw0.y));
        fma_h8(acc, r1, __int_as_float(sw1.y));
    }
    if (e < end) {
        const int2 sw = __ldcs(&g_sw[e]);
        const uint4 r = __ldg(
            reinterpret_cast<const uint4*>(g_Hh + (size_t)sw.x * D) + hl);
        fma_h8(acc, r, __int_as_float(sw.y));
    }

    // Residual + relu, 8 floats per lane (32B) = two float4.
    const float4* xp = reinterpret_cast<const float4*>(X + (size_t)node * D) + hl * 2;
    float4* op = reinterpret_cast<float4*>(out + (size_t)node * D) + hl * 2;
    const float4 xv0 = __ldcs(xp);
    const float4 xv1 = __ldcs(xp + 1);
    float4 o0, o1;
    o0.x = fmaxf(acc[0], 0.f) + xv0.x;
    o0.y = fmaxf(acc[1], 0.f) + xv0.y;
    o0.z = fmaxf(acc[2], 0.f) + xv0.z;
    o0.w = fmaxf(acc[3], 0.f) + xv0.w;
    o1.x = fmaxf(acc[4], 0.f) + xv1.x;
    o1.y = fmaxf(acc[5], 0.f) + xv1.y;
    o1.z = fmaxf(acc[6], 0.f) + xv1.z;
    o1.w = fmaxf(acc[7], 0.f) + xv1.w;
    __stcs(op, o0);
    __stcs(op + 1, o1);
}

// ===========================================================================
extern "C" void kernel_launch(void* const* d_in, const int* in_sizes, int n_in,
                              void* d_out, int out_size) {
    const float* X     = (const float*)d_in[0];
    const int*   esrc  = (const int*)d_in[1];
    const int*   edst  = (const int*)d_in[2];
    const float* ew    = (const float*)d_in[3];
    const float* gamma = (const float*)d_in[4];
    const float* beta  = (const float*)d_in[5];
    const float* W     = (const float*)d_in[6];
    const float* bias  = (const float*)d_in[7];
    float* out         = (float*)d_out;
    const int E        = in_sizes[1];

    cudaFuncSetAttribute(ln_linear_hist_kernel,
                         cudaFuncAttributeMaxDynamicSharedMemorySize,
                         SMEM_BYTES);

    void* off_ptr = nullptr;
    cudaGetSymbolAddress(&off_ptr, g_off);
    cudaMemsetAsync(off_ptr, 0, (N_NODES + 1) * sizeof(int));

    const int n  = N_NODES + 1;
    const int nb = (n + 1023) / 1024;                 // 98

    ln_linear_hist_kernel<<<LN_BLOCKS + HIST_BLOCKS, 256, SMEM_BYTES>>>(
        X, gamma, beta, W, bias, edst, E);

    scan_chunk_kernel<<<nb, 1024>>>(n);
    scan_bsum_kernel<<<1, 128>>>(nb);
    scan_add_kernel<<<nb, 1024>>>(n);
    reorder_kernel<<<1024, 256>>>(esrc, edst, ew, E);

    // 2 nodes per warp -> 50000 warps -> 6250 blocks of 256.
    aggregate_kernel<<<(N_NODES / 2 * 32 + 255) / 256, 256>>>(X, out);
}

// round 9
// speedup vs baseline: 1.0479x; 1.0479x over previous
#include <cuda_runtime.h>
#include <cuda_fp16.h>
#include <stdint.h>

#define N_NODES 100000
#define N_EDGES 3200000
#define D 128
#define LN_EPS 1e-5f

// ---------------------------------------------------------------------------
// Device-global scratch (no allocations allowed).
// ---------------------------------------------------------------------------
__device__ __half g_Hh[(size_t)N_NODES * D];   // LN(X) @ W^T + b, fp16
__device__ int   g_off[N_NODES + 1];           // CSR offsets (by dst)
__device__ int   g_cur[N_NODES];               // bucket cursors
__device__ int2  g_sw[N_EDGES];                // packed (src, w_bits) sorted by dst
__device__ int   g_bsum[128];                  // scan block sums

// ===========================================================================
// Kernel 1: fused [LayerNorm + Linear -> g_Hh (fp16)]  +  [edge histogram].
// ===========================================================================
#define ROWS_PB 32
#define LN_BLOCKS (N_NODES / ROWS_PB)              // 3125
#define HIST_BLOCKS 1024
#define WS_PITCH 132
#define XN2_OFF (128 * WS_PITCH)                   // in floats
#define SMEM_BYTES ((128 * WS_PITCH) * 4 + ROWS_PB * D * 8)

__global__ void __launch_bounds__(256, 2)
ln_linear_hist_kernel(const float* __restrict__ X,
                      const float* __restrict__ gamma,
                      const float* __restrict__ beta,
                      const float* __restrict__ W,
                      const float* __restrict__ bias,
                      const int* __restrict__ edst, int E) {
    const int tid = threadIdx.x;

    // ---- histogram role -------------------------------------------------
    if (blockIdx.x >= LN_BLOCKS) {
        const int hb     = blockIdx.x - LN_BLOCKS;
        const int stride = HIST_BLOCKS * 256;
        for (int e = hb * 256 + tid; e < E; e += stride)
            atomicAdd(&g_off[__ldcs(&edst[e]) + 1], 1);
        return;
    }

    // ---- LN + GEMM role -------------------------------------------------
    extern __shared__ float smem[];
    float*  Ws  = smem;                                       // [128][132]
    float2* xn2 = reinterpret_cast<float2*>(smem + XN2_OFF);  // splatted {x,x}

    const int lane = tid & 31;
    const int warp = tid >> 5;
    const int row0 = blockIdx.x * ROWS_PB;

    // Load + transpose W into smem.
    for (int i = tid; i < 128 * 128; i += 256) {
        int o = i >> 7;
        int d = i & 127;
        Ws[d * WS_PITCH + o] = W[i];
    }

    // LayerNorm: 8 warps x 4 rows each; write splatted pairs {h,h}.
    #pragma unroll
    for (int rr = 0; rr < ROWS_PB / 8; ++rr) {
        const int r   = warp + rr * 8;
        const int row = row0 + r;
        const float4 v = reinterpret_cast<const float4*>(X + (size_t)row * D)[lane];
        float s  = v.x + v.y + v.z + v.w;
        float sq = v.x * v.x + v.y * v.y + v.z * v.z + v.w * v.w;
        #pragma unroll
        for (int off = 16; off; off >>= 1) {
            s  += __shfl_xor_sync(0xffffffffu, s,  off);
            sq += __shfl_xor_sync(0xffffffffu, sq, off);
        }
        const float mu  = s * (1.0f / D);
        const float var = sq * (1.0f / D) - mu * mu;
        const float inv = rsqrtf(var + LN_EPS);
        const float4 g  = reinterpret_cast<const float4*>(gamma)[lane];
        const float4 be = reinterpret_cast<const float4*>(beta)[lane];
        float h0 = (v.x - mu) * inv * g.x + be.x;
        float h1 = (v.y - mu) * inv * g.y + be.y;
        float h2 = (v.z - mu) * inv * g.z + be.z;
        float h3 = (v.w - mu) * inv * g.w + be.w;
        float2* xp = xn2 + r * D + lane * 4;
        xp[0] = make_float2(h0, h0);
        xp[1] = make_float2(h1, h1);
        xp[2] = make_float2(h2, h2);
        xp[3] = make_float2(h3, h3);
    }
    __syncthreads();

    // GEMM: thread (tr, tc): rows tr*4..+3, cols tc*4..+3. f32x2 packed FMA.
    const int tc = tid & 31;
    const int tr = tid >> 5;

    unsigned long long acc01[4], acc23[4];
    #pragma unroll
    for (int i = 0; i < 4; ++i) { acc01[i] = 0ull; acc23[i] = 0ull; }

    const unsigned long long* xbase =
        reinterpret_cast<const unsigned long long*>(xn2) + tr * 4 * D;
    const float* wbase = Ws + (tc << 2);

    #pragma unroll 4
    for (int d = 0; d < D; ++d) {
        const ulonglong2 wv =
            *reinterpret_cast<const ulonglong2*>(wbase + d * WS_PITCH);
        #pragma unroll
        for (int r = 0; r < 4; ++r) {
            const unsigned long long xs = xbase[r * D + d];   // {x,x}
            asm("fma.rn.f32x2 %0, %1, %2, %0;" : "+l"(acc01[r]) : "l"(xs), "l"(wv.x));
            asm("fma.rn.f32x2 %0, %1, %2, %0;" : "+l"(acc23[r]) : "l"(xs), "l"(wv.y));
        }
    }

    const float4 bv = reinterpret_cast<const float4*>(bias)[tc];
    #pragma unroll
    for (int r = 0; r < 4; ++r) {
        const int row = row0 + tr * 4 + r;
        const float hx = __uint_as_float((unsigned)(acc01[r] & 0xffffffffull)) + bv.x;
        const float hy = __uint_as_float((unsigned)(acc01[r] >> 32))           + bv.y;
        const float hz = __uint_as_float((unsigned)(acc23[r] & 0xffffffffull)) + bv.z;
        const float hw = __uint_as_float((unsigned)(acc23[r] >> 32))           + bv.w;
        const __half2 p01 = __floats2half2_rn(hx, hy);
        const __half2 p23 = __floats2half2_rn(hz, hw);
        uint2 st;
        st.x = *reinterpret_cast<const unsigned*>(&p01);
        st.y = *reinterpret_cast<const unsigned*>(&p23);
        reinterpret_cast<uint2*>(g_Hh + (size_t)row * D)[tc] = st;
    }
}

// ===========================================================================
// CSR build: scan + reorder (histogram fused above)
// ===========================================================================
__device__ __forceinline__ int warp_incl_scan(int v, int lane) {
    #pragma unroll
    for (int off = 1; off < 32; off <<= 1) {
        int t = __shfl_up_sync(0xffffffffu, v, off);
        if (lane >= off) v += t;
    }
    return v;
}

__global__ void scan_chunk_kernel(int n) {        // blockDim = 1024
    __shared__ int wsum[32];
    const int tid  = threadIdx.x;
    const int lane = tid & 31;
    const int wid  = tid >> 5;
    const int gi   = blockIdx.x * 1024 + tid;
    int v = (gi < n) ? g_off[gi] : 0;
    v = warp_incl_scan(v, lane);
    if (lane == 31) wsum[wid] = v;
    __syncthreads();
    if (wid == 0) wsum[lane] = warp_incl_scan(wsum[lane], lane);
    __syncthreads();
    if (wid > 0) v += wsum[wid - 1];
    if (gi < n) g_off[gi] = v;
    if (tid == 1023) g_bsum[blockIdx.x] = v;
}

__global__ void scan_bsum_kernel(int nb) {        // 1 block, 128 threads
    __shared__ int wsum[4];
    const int tid  = threadIdx.x;
    const int lane = tid & 31;
    const int wid  = tid >> 5;
    int v = (tid < nb) ? g_bsum[tid] : 0;
    v = warp_incl_scan(v, lane);
    if (lane == 31) wsum[wid] = v;
    __syncthreads();
    int add = 0;
    #pragma unroll
    for (int w = 0; w < 4; ++w) add += (w < wid) ? wsum[w] : 0;
    if (tid < nb) g_bsum[tid] = v + add;
}

__global__ void scan_add_kernel(int n) {          // blockDim = 1024
    const int gi = blockIdx.x * 1024 + threadIdx.x;
    if (gi >= n) return;
    const int add = (blockIdx.x > 0) ? g_bsum[blockIdx.x - 1] : 0;
    const int val = g_off[gi] + add;
    g_off[gi] = val;
    if (gi < N_NODES) g_cur[gi] = val;
}

__global__ void reorder_kernel(const int* __restrict__ esrc,
                               const int* __restrict__ edst,
                               const float* __restrict__ ew, int E) {
    const int stride = gridDim.x * blockDim.x;
    for (int e = blockIdx.x * blockDim.x + threadIdx.x; e < E; e += stride) {
        const int dst = __ldcs(&edst[e]);
        const int pos = atomicAdd(&g_cur[dst], 1);
        g_sw[pos] = make_int2(__ldcs(&esrc[e]), __float_as_int(__ldcs(&ew[e])));
    }
}

// ===========================================================================
// Aggregate: one warp per dst node, unroll-4 with front-batched gathers.
//   Lane loads uint2 = 8B of the 256B fp16 row; fp32 accumulate.
//   out = relu(sum w*H[src]) + X.
// ===========================================================================
__device__ __forceinline__ void fma_h4(float4& acc, uint2 raw, float w) {
    const __half2 a = *reinterpret_cast<const __half2*>(&raw.x);
    const __half2 b = *reinterpret_cast<const __half2*>(&raw.y);
    const float2 f01 = __half22float2(a);
    const float2 f23 = __half22float2(b);
    acc.x = fmaf(w, f01.x, acc.x);
    acc.y = fmaf(w, f01.y, acc.y);
    acc.z = fmaf(w, f23.x, acc.z);
    acc.w = fmaf(w, f23.y, acc.w);
}

__global__ void __launch_bounds__(256)
aggregate_kernel(const float* __restrict__ X, float* __restrict__ out) {
    const int gw = (blockIdx.x * blockDim.x + threadIdx.x) >> 5;
    if (gw >= N_NODES) return;
    const int lane = threadIdx.x & 31;

    const int beg = g_off[gw];
    const int end = g_off[gw + 1];

    float4 acc = make_float4(0.f, 0.f, 0.f, 0.f);
    int e = beg;

    // Unroll-4: batch the 4 edge reads, then the 4 row gathers (MLP~5).
    for (; e + 3 < end; e += 4) {
        const int2 sw0 = __ldcs(&g_sw[e]);
        const int2 sw1 = __ldcs(&g_sw[e + 1]);
        const int2 sw2 = __ldcs(&g_sw[e + 2]);
        const int2 sw3 = __ldcs(&g_sw[e + 3]);
        const uint2 r0 = __ldg(
            reinterpret_cast<const uint2*>(g_Hh + (size_t)sw0.x * D) + lane);
        const uint2 r1 = __ldg(
            reinterpret_cast<const uint2*>(g_Hh + (size_t)sw1.x * D) + lane);
        const uint2 r2 = __ldg(
            reinterpret_cast<const uint2*>(g_Hh + (size_t)sw2.x * D) + lane);
        const uint2 r3 = __ldg(
            reinterpret_cast<const uint2*>(g_Hh + (size_t)sw3.x * D) + lane);
        fma_h4(acc, r0, __int_as_float(sw0.y));
        fma_h4(acc, r1, __int_as_float(sw1.y));
        fma_h4(acc, r2, __int_as_float(sw2.y));
        fma_h4(acc, r3, __int_as_float(sw3.y));
    }
    for (; e < end; ++e) {
        const int2 sw = __ldcs(&g_sw[e]);
        const uint2 r = __ldg(
            reinterpret_cast<const uint2*>(g_Hh + (size_t)sw.x * D) + lane);
        fma_h4(acc, r, __int_as_float(sw.y));
    }

    const float4 xv =
        __ldcs(reinterpret_cast<const float4*>(X + (size_t)gw * D) + lane);
    float4 o;
    o.x = fmaxf(acc.x, 0.f) + xv.x;
    o.y = fmaxf(acc.y, 0.f) + xv.y;
    o.z = fmaxf(acc.z, 0.f) + xv.z;
    o.w = fmaxf(acc.w, 0.f) + xv.w;
    __stcs(reinterpret_cast<float4*>(out + (size_t)gw * D) + lane, o);
}

// ===========================================================================
extern "C" void kernel_launch(void* const* d_in, const int* in_sizes, int n_in,
                              void* d_out, int out_size) {
    const float* X     = (const float*)d_in[0];
    const int*   esrc  = (const int*)d_in[1];
    const int*   edst  = (const int*)d_in[2];
    const float* ew    = (const float*)d_in[3];
    const float* gamma = (const float*)d_in[4];
    const float* beta  = (const float*)d_in[5];
    const float* W     = (const float*)d_in[6];
    const float* bias  = (const float*)d_in[7];
    float* out         = (float*)d_out;
    const int E        = in_sizes[1];

    cudaFuncSetAttribute(ln_linear_hist_kernel,
                         cudaFuncAttributeMaxDynamicSharedMemorySize,
                         SMEM_BYTES);

    void* off_ptr = nullptr;
    cudaGetSymbolAddress(&off_ptr, g_off);
    cudaMemsetAsync(off_ptr, 0, (N_NODES + 1) * sizeof(int));

    const int n  = N_NODES + 1;
    const int nb = (n + 1023) / 1024;                 // 98

    ln_linear_hist_kernel<<<LN_BLOCKS + HIST_BLOCKS, 256, SMEM_BYTES>>>(
        X, gamma, beta, W, bias, edst, E);

    scan_chunk_kernel<<<nb, 1024>>>(n);
    scan_bsum_kernel<<<1, 128>>>(nb);
    scan_add_kernel<<<nb, 1024>>>(n);
    reorder_kernel<<<1024, 256>>>(esrc, edst, ew, E);

    aggregate_kernel<<<(N_NODES * 32 + 255) / 256, 256>>>(X, out);
}